// round 13
// baseline (speedup 1.0000x reference)
#include <cuda_runtime.h>
#include <cstdint>

#define Bq 256
#define Nn 256
#define Dd 1024
#define Ss 1024

// K1 tiling
#define STG_P 132
#define OFF_STAGE 0
#define STAGE_F (2 * 32 * STG_P)       // 8448
#define OFF_BFH STAGE_F                // B frags hi (double): 2*4096
#define OFF_BFL (OFF_BFH + 8192)       // B frags lo (double): 2*4096
#define OFF_RED (OFF_BFL + 8192)       // fm[128] + redm[512] + reds[512]
#define SMEM_F (OFF_RED + 1152)
#define SMEM_BYTES (SMEM_F * 4)        // 104960 B

// Scratch (device globals — no allocation APIs anywhere)
__device__ float    g_A[Bq * Ss];
__device__ float    g_M[Bq * Nn];
__device__ uint32_t g_Ahi[Bq * Nn];       // A fragments, tf32 hi
__device__ uint32_t g_Alo[Bq * Nn];       // A fragments, tf32 lo
__device__ float    g_stats[Bq * Bq * 16]; // per (i,b,nt 0..7): m, s
__device__ float    g_ctx_scratch[Bq * Dd];

// ---------------------------------------------------------------------------
__global__ void gemm_A_kernel(const float* __restrict__ state,
                              const float* __restrict__ Q) {
    __shared__ float sS[32][33];
    __shared__ float sQ[32][33];
    int tx = threadIdx.x, ty = threadIdx.y;
    int t = ty * 16 + tx;
    int b0 = blockIdx.y * 32, s0 = blockIdx.x * 32;
    float acc00 = 0.f, acc01 = 0.f, acc10 = 0.f, acc11 = 0.f;
    for (int k0 = 0; k0 < Ss; k0 += 32) {
        #pragma unroll
        for (int l = t; l < 1024; l += 256) {
            int r = l >> 5, c = l & 31;
            sS[r][c] = state[(b0 + r) * Ss + k0 + c];
            sQ[r][c] = Q[(s0 + r) * Ss + k0 + c];
        }
        __syncthreads();
        #pragma unroll
        for (int kk = 0; kk < 32; kk++) {
            float a0 = sS[2 * ty][kk],     a1 = sS[2 * ty + 1][kk];
            float q0 = sQ[2 * tx][kk],     q1 = sQ[2 * tx + 1][kk];
            acc00 = fmaf(a0, q0, acc00);
            acc01 = fmaf(a0, q1, acc01);
            acc10 = fmaf(a1, q0, acc10);
            acc11 = fmaf(a1, q1, acc11);
        }
        __syncthreads();
    }
    g_A[(b0 + 2 * ty)     * Ss + s0 + 2 * tx]     = acc00;
    g_A[(b0 + 2 * ty)     * Ss + s0 + 2 * tx + 1] = acc01;
    g_A[(b0 + 2 * ty + 1) * Ss + s0 + 2 * tx]     = acc10;
    g_A[(b0 + 2 * ty + 1) * Ss + s0 + 2 * tx + 1] = acc11;
}

__global__ void gemm_M_kernel(const float* __restrict__ Km) {
    __shared__ float sA[32][33];
    __shared__ float sK[32][33];
    int tx = threadIdx.x, ty = threadIdx.y;
    int t = ty * 16 + tx;
    int b0 = blockIdx.y * 32, n0 = blockIdx.x * 32;
    float acc00 = 0.f, acc01 = 0.f, acc10 = 0.f, acc11 = 0.f;
    for (int kc = 0; kc < Ss; kc += 32) {
        #pragma unroll
        for (int l = t; l < 1024; l += 256) {
            int r = l >> 5, c = l & 31;
            sA[r][c] = g_A[(b0 + r) * Ss + kc + c];
            sK[r][c] = Km[(kc + r) * Nn + n0 + c];
        }
        __syncthreads();
        #pragma unroll
        for (int kk = 0; kk < 32; kk++) {
            float a0 = sA[2 * ty][kk],     a1 = sA[2 * ty + 1][kk];
            float b0v = sK[kk][2 * tx],    b1v = sK[kk][2 * tx + 1];
            acc00 = fmaf(a0, b0v, acc00);
            acc01 = fmaf(a0, b1v, acc01);
            acc10 = fmaf(a1, b0v, acc10);
            acc11 = fmaf(a1, b1v, acc11);
        }
        __syncthreads();
    }
    g_M[(b0 + 2 * ty)     * Nn + n0 + 2 * tx]     = acc00;
    g_M[(b0 + 2 * ty)     * Nn + n0 + 2 * tx + 1] = acc01;
    g_M[(b0 + 2 * ty + 1) * Nn + n0 + 2 * tx]     = acc10;
    g_M[(b0 + 2 * ty + 1) * Nn + n0 + 2 * tx + 1] = acc11;
}

// ---------------------------------------------------------------------------
__device__ __forceinline__ void cp_async16(uint32_t saddr, const void* gptr) {
    asm volatile("cp.async.cg.shared.global [%0], [%1], 16;\n"
                 :: "r"(saddr), "l"(gptr));
}
__device__ __forceinline__ uint32_t f2tf(float x) {
    uint32_t r;
    asm("cvt.rna.tf32.f32 %0, %1;" : "=r"(r) : "f"(x));
    return r;
}
__device__ __forceinline__ void tfsplit(float x, uint32_t& hi, uint32_t& lo) {
    hi = f2tf(x);
    lo = f2tf(x - __uint_as_float(hi));
}
__device__ __forceinline__ void mma_tf32(float* c, const uint32_t* a,
                                         uint32_t b0, uint32_t b1) {
    asm volatile(
        "mma.sync.aligned.m16n8k8.row.col.f32.tf32.tf32.f32 "
        "{%0,%1,%2,%3}, {%4,%5,%6,%7}, {%8,%9}, {%0,%1,%2,%3};"
        : "+f"(c[0]), "+f"(c[1]), "+f"(c[2]), "+f"(c[3])
        : "r"(a[0]), "r"(a[1]), "r"(a[2]), "r"(a[3]), "r"(b0), "r"(b1));
}

// ---------------------------------------------------------------------------
// A pre-split: g_M -> tf32 hi/lo in mma fragment order.
__global__ void afrag_kernel() {
    int wg = blockIdx.x * 8 + (threadIdx.x >> 5);   // kg*16 + mtile
    int l  = threadIdx.x & 31;
    int m0 = (wg & 15) * 16 + (l >> 2);
    int k0 = (wg >> 4) * 8 + (l & 3);
    float x0 = g_M[m0 * Nn + k0];
    float x1 = g_M[(m0 + 8) * Nn + k0];
    float x2 = g_M[m0 * Nn + k0 + 4];
    float x3 = g_M[(m0 + 8) * Nn + k0 + 4];
    uint4 h, lo;
    tfsplit(x0, h.x, lo.x); tfsplit(x1, h.y, lo.y);
    tfsplit(x2, h.z, lo.z); tfsplit(x3, h.w, lo.w);
    *(uint4*)(g_Ahi + (size_t)(wg * 32 + l) * 4) = h;
    *(uint4*)(g_Alo + (size_t)(wg * 32 + l) * 4) = lo;
}

// ---------------------------------------------------------------------------
// K1: 3-pass tf32 mma.sync. CTA=(nt,mt,i): C[128 m][128 d], k=256 (8 chunks).
// ONE __syncthreads per chunk: each warp cp.asyncs exactly the stage region
// its own convert reads (warp-private), so stage readiness needs only its own
// wait_group; frag buffers are double-buffered and convert(c+1) interleaves
// with mma(c).
__global__ void __launch_bounds__(512, 1)
wpre_mma_kernel(const float* __restrict__ FV, float* __restrict__ Wout) {
    extern __shared__ float smem[];
    uint32_t* smu = (uint32_t*)smem;
    const int i  = blockIdx.z;
    const int mt = blockIdx.y;
    const int nt = blockIdx.x;
    const int b0 = mt * 128;
    const int d0 = nt * 128;
    const int tid = threadIdx.x;
    const int w = tid >> 5, l = tid & 31;
    const int mw = w & 3, nw = w >> 2;
    const int cks = w >> 2, cjp = (w & 3) * 2;
    const float* FVi = FV + (size_t)i * Nn * Dd;
    const uint32_t sbase = (uint32_t)__cvta_generic_to_shared(smem);

    // warp-private stage region: rows [8cks, 8cks+8) x cols [16cjp, 16cjp+32)
    const int srow = 8 * cks + (l >> 2);
    const int scol = 16 * cjp + (l & 3) * 4;
    auto issue_stage = [&](int c) {
        const float* src = FVi + (size_t)(c * 32 + srow) * Dd + d0 + scol;
        uint32_t dst = sbase
            + (uint32_t)((c & 1) * 32 * STG_P + srow * STG_P + scol) * 4;
        cp_async16(dst, src);
        cp_async16(dst + 64, src + 16);
        asm volatile("cp.async.commit_group;\n");
    };

    // convert chunk c from stage[(c)&1] into frag buffer (c)&1
    auto convert_chunk = [&](int c) {
        const float* stg = smem + OFF_STAGE + (c & 1) * 32 * STG_P;
        const int fb = (c & 1) * 4096;
        #pragma unroll
        for (int jj = 0; jj < 2; jj++) {
            int jp = cjp + jj;
            uint4 h, lo;
            #pragma unroll
            for (int sub = 0; sub < 4; sub++) {
                int j = jp * 2 + (sub >> 1);
                int r = sub & 1;
                int k = cks * 8 + r * 4 + (l & 3);
                int d = j * 8 + (l >> 2);
                float x = stg[k * STG_P + d];
                tfsplit(x, ((uint32_t*)&h)[sub], ((uint32_t*)&lo)[sub]);
            }
            int word = fb + ((cks * 8 + jp) * 32 + l) * 4;
            *(uint4*)(smu + OFF_BFH + word) = h;
            *(uint4*)(smu + OFF_BFL + word) = lo;
        }
    };

    float acc[2][4][4];
    #pragma unroll
    for (int a = 0; a < 2; a++)
        #pragma unroll
        for (int b = 0; b < 4; b++)
            #pragma unroll
            for (int c = 0; c < 4; c++) acc[a][b][c] = 0.f;

    // one ks-block of mma for chunk buffer fb
    auto mma_ks = [&](int c, int ks) {
        const int kg = c * 4 + ks;
        const int fb = (c & 1) * 4096;
        uint4 ah[2], al[2];
        #pragma unroll
        for (int mi = 0; mi < 2; mi++) {
            int mtile = mt * 8 + mw * 2 + mi;
            size_t aw = (size_t)((kg * 16 + mtile) * 32 + l) * 4;
            ah[mi] = *(const uint4*)(g_Ahi + aw);
            al[mi] = *(const uint4*)(g_Alo + aw);
        }
        uint4 bh[2], bl[2];
        #pragma unroll
        for (int p = 0; p < 2; p++) {
            int word = fb + ((ks * 8 + nw * 2 + p) * 32 + l) * 4;
            bh[p] = *(const uint4*)(smu + OFF_BFH + word);
            bl[p] = *(const uint4*)(smu + OFF_BFL + word);
        }
        #pragma unroll
        for (int mi = 0; mi < 2; mi++) {
            #pragma unroll
            for (int j = 0; j < 4; j++) {
                int p = j >> 1, hf = j & 1;
                uint32_t bh0 = hf ? bh[p].z : bh[p].x;
                uint32_t bh1 = hf ? bh[p].w : bh[p].y;
                uint32_t bl0 = hf ? bl[p].z : bl[p].x;
                uint32_t bl1 = hf ? bl[p].w : bl[p].y;
                mma_tf32(acc[mi][j], (const uint32_t*)&ah[mi], bh0, bh1);
                mma_tf32(acc[mi][j], (const uint32_t*)&ah[mi], bl0, bl1);
                mma_tf32(acc[mi][j], (const uint32_t*)&al[mi], bh0, bh1);
            }
        }
    };

    // prologue
    issue_stage(0);
    issue_stage(1);
    asm volatile("cp.async.wait_group 1;\n");   // own stage-0 region landed
    convert_chunk(0);
    __syncthreads();                            // frag[0] published

    for (int c = 0; c < 8; c++) {
        if (c + 2 < 8) issue_stage(c + 2);
        if (c + 1 < 8) {
            if (c + 2 < 8) { asm volatile("cp.async.wait_group 1;\n"); }
            else           { asm volatile("cp.async.wait_group 0;\n"); }
        }
        // interleave mma(c) with convert(c+1)
        mma_ks(c, 0);
        mma_ks(c, 1);
        if (c + 1 < 8) convert_chunk(c + 1);
        mma_ks(c, 2);
        mma_ks(c, 3);
        __syncthreads();                        // frag[(c+1)&1] published
    }

    // ---- epilogue: per-row tile stats + pre-softmax W store
    float* fm   = smem + OFF_RED;
    float* redm = fm + 128;
    float* reds = redm + 512;

    #pragma unroll
    for (int mi = 0; mi < 2; mi++) {
        #pragma unroll
        for (int h = 0; h < 2; h++) {
            float m = -3.4e38f;
            #pragma unroll
            for (int j = 0; j < 4; j++)
                m = fmaxf(m, fmaxf(acc[mi][j][2 * h], acc[mi][j][2 * h + 1]));
            m = fmaxf(m, __shfl_xor_sync(0xffffffffu, m, 1));
            m = fmaxf(m, __shfl_xor_sync(0xffffffffu, m, 2));
            if ((l & 3) == 0)
                redm[nw * 128 + mw * 32 + mi * 16 + (l >> 2) + 8 * h] = m;
        }
    }
    __syncthreads();
    if (tid < 128)
        fm[tid] = fmaxf(fmaxf(redm[tid], redm[128 + tid]),
                        fmaxf(redm[256 + tid], redm[384 + tid]));
    __syncthreads();
    #pragma unroll
    for (int mi = 0; mi < 2; mi++) {
        #pragma unroll
        for (int h = 0; h < 2; h++) {
            int row = mw * 32 + mi * 16 + (l >> 2) + 8 * h;
            float m = fm[row];
            float s = 0.f;
            #pragma unroll
            for (int j = 0; j < 4; j++)
                s += __expf(acc[mi][j][2 * h] - m) + __expf(acc[mi][j][2 * h + 1] - m);
            s += __shfl_xor_sync(0xffffffffu, s, 1);
            s += __shfl_xor_sync(0xffffffffu, s, 2);
            if ((l & 3) == 0) reds[nw * 128 + row] = s;
        }
    }
    __syncthreads();
    if (tid < 128) {
        int sidx = (((i * Bq) + b0 + tid) * 8 + nt) * 2;
        g_stats[sidx]     = fm[tid];
        g_stats[sidx + 1] = (reds[tid] + reds[128 + tid])
                          + (reds[256 + tid] + reds[384 + tid]);
    }
    #pragma unroll
    for (int mi = 0; mi < 2; mi++) {
        #pragma unroll
        for (int h = 0; h < 2; h++) {
            int row = mw * 32 + mi * 16 + (l >> 2) + 8 * h;
            float* wr = Wout + ((size_t)i * Bq + b0 + row) * Dd
                      + d0 + nw * 32 + 2 * (l & 3);
            #pragma unroll
            for (int j = 0; j < 4; j++)
                *(float2*)(wr + j * 8) =
                    make_float2(acc[mi][j][2 * h], acc[mi][j][2 * h + 1]);
        }
    }
}

// ---------------------------------------------------------------------------
// K2: float4 streaming softmax+context; 1024 CTAs x 256 thr for balance.
__global__ void __launch_bounds__(256)
softmax_ctx_kernel(const float* __restrict__ FV,
                   float* __restrict__ W,
                   float* __restrict__ ctx) {
    __shared__ float  sm_m[256], sm_inv[256];
    __shared__ float4 cpart[4][64];
    const int i  = blockIdx.y;
    const int dh = blockIdx.x;
    const int t  = threadIdx.x;
    const int g  = t >> 6;          // b-group 0..3
    const int tl = t & 63;
    const int d  = dh * 256 + tl * 4;

    {
        int b = t;
        const float* st = g_stats + (size_t)(i * Bq + b) * 16;
        float m = st[0];
        #pragma unroll
        for (int k = 1; k < 8; k++) m = fmaxf(m, st[2 * k]);
        float s = 0.f;
        #pragma unroll
        for (int k = 0; k < 8; k++) s += st[2 * k + 1] * __expf(st[2 * k] - m);
        sm_m[b]   = m;
        sm_inv[b] = 1.f / s;
    }
    __syncthreads();

    const float4* Wv  = (const float4*)(W  + (size_t)i * Bq * Dd + d);
    float4*       Wo  = (float4*)(W  + (size_t)i * Bq * Dd + d);
    const float4* FVv = (const float4*)(FV + (size_t)i * Nn * Dd + d);
    const int strd = Dd / 4;

    float4 acc = make_float4(0.f, 0.f, 0.f, 0.f);
    #pragma unroll 4
    for (int it = 0; it < 64; it++) {
        int b = g + it * 4;
        float4 x = __ldcs(Wv + (size_t)b * strd);
        float m = sm_m[b], inv = sm_inv[b];
        float4 wv;
        wv.x = __expf(x.x - m) * inv;
        wv.y = __expf(x.y - m) * inv;
        wv.z = __expf(x.z - m) * inv;
        wv.w = __expf(x.w - m) * inv;
        __stcs(Wo + (size_t)b * strd, wv);
        float4 f = __ldcs(FVv + (size_t)b * strd);
        acc.x = fmaf(wv.x, f.x, acc.x);
        acc.y = fmaf(wv.y, f.y, acc.y);
        acc.z = fmaf(wv.z, f.z, acc.z);
        acc.w = fmaf(wv.w, f.w, acc.w);
    }
    cpart[g][tl] = acc;
    __syncthreads();
    if (g == 0) {
        float4 a0 = cpart[0][tl], a1 = cpart[1][tl];
        float4 a2 = cpart[2][tl], a3 = cpart[3][tl];
        float4 r;
        r.x = (a0.x + a1.x) + (a2.x + a3.x);
        r.y = (a0.y + a1.y) + (a2.y + a3.y);
        r.z = (a0.z + a1.z) + (a2.z + a3.z);
        r.w = (a0.w + a1.w) + (a2.w + a3.w);
        *(float4*)(ctx + (size_t)i * Dd + d) = r;
    }
}

// ---------------------------------------------------------------------------
extern "C" void kernel_launch(void* const* d_in, const int* in_sizes, int n_in,
                              void* d_out, int out_size) {
    const float* FV    = (const float*)d_in[0];
    const float* state = (const float*)d_in[1];
    const float* Q     = (const float*)d_in[2];
    const float* Km    = (const float*)d_in[3];
    float* out = (float*)d_out;

    const long long wsz = (long long)Bq * Bq * Dd;
    float* ctxp;
    float* Wp;
    if ((long long)out_size == wsz) {
        Wp = out;
        cudaGetSymbolAddress((void**)&ctxp, g_ctx_scratch);
    } else {
        ctxp = out;
        Wp   = out + (size_t)Bq * Dd;
    }

    cudaFuncSetAttribute(wpre_mma_kernel,
                         cudaFuncAttributeMaxDynamicSharedMemorySize, SMEM_BYTES);

    gemm_A_kernel<<<dim3(Ss / 32, Bq / 32), dim3(16, 16)>>>(state, Q);
    gemm_M_kernel<<<dim3(Nn / 32, Bq / 32), dim3(16, 16)>>>(Km);
    afrag_kernel<<<64, 256>>>();
    wpre_mma_kernel<<<dim3(8, 2, 256), 512, SMEM_BYTES>>>(FV, Wp);
    softmax_ctx_kernel<<<dim3(4, 256), 256>>>(FV, Wp, ctxp);
}

// round 14
// speedup vs baseline: 1.0152x; 1.0152x over previous
#include <cuda_runtime.h>
#include <cstdint>

#define Bq 256
#define Nn 256
#define Dd 1024
#define Ss 1024

// K1 tiling (R6/R11-proven layout)
#define STG_P 132
#define OFF_STAGE 0
#define STAGE_F (2 * 32 * STG_P)       // 8448
#define OFF_BFH STAGE_F                // B frags hi: 4 ks * 8 jp * 32 * 4 = 4096
#define OFF_BFL (OFF_BFH + 4096)
#define OFF_RED (OFF_BFL + 4096)       // fm[128] + redm[4][128] + reds[4][128]
#define SMEM_F (OFF_RED + 1152)
#define SMEM_BYTES (SMEM_F * 4)        // 71168 B

// Scratch (device globals — no allocation APIs anywhere)
__device__ float    g_A[Bq * Ss];
__device__ float    g_M[Bq * Nn];
__device__ uint32_t g_Ahi[Bq * Nn];       // A fragments, tf32 hi
__device__ uint32_t g_Alo[Bq * Nn];       // A fragments, tf32 lo
__device__ float    g_stats[Bq * Bq * 16]; // per (i,b,nt 0..7): m, s
__device__ float    g_ctx_scratch[Bq * Dd];

// ---------------------------------------------------------------------------
__global__ void gemm_A_kernel(const float* __restrict__ state,
                              const float* __restrict__ Q) {
    __shared__ float sS[32][33];
    __shared__ float sQ[32][33];
    int tx = threadIdx.x, ty = threadIdx.y;
    int t = ty * 16 + tx;
    int b0 = blockIdx.y * 32, s0 = blockIdx.x * 32;
    float acc00 = 0.f, acc01 = 0.f, acc10 = 0.f, acc11 = 0.f;
    for (int k0 = 0; k0 < Ss; k0 += 32) {
        #pragma unroll
        for (int l = t; l < 1024; l += 256) {
            int r = l >> 5, c = l & 31;
            sS[r][c] = state[(b0 + r) * Ss + k0 + c];
            sQ[r][c] = Q[(s0 + r) * Ss + k0 + c];
        }
        __syncthreads();
        #pragma unroll
        for (int kk = 0; kk < 32; kk++) {
            float a0 = sS[2 * ty][kk],     a1 = sS[2 * ty + 1][kk];
            float q0 = sQ[2 * tx][kk],     q1 = sQ[2 * tx + 1][kk];
            acc00 = fmaf(a0, q0, acc00);
            acc01 = fmaf(a0, q1, acc01);
            acc10 = fmaf(a1, q0, acc10);
            acc11 = fmaf(a1, q1, acc11);
        }
        __syncthreads();
    }
    g_A[(b0 + 2 * ty)     * Ss + s0 + 2 * tx]     = acc00;
    g_A[(b0 + 2 * ty)     * Ss + s0 + 2 * tx + 1] = acc01;
    g_A[(b0 + 2 * ty + 1) * Ss + s0 + 2 * tx]     = acc10;
    g_A[(b0 + 2 * ty + 1) * Ss + s0 + 2 * tx + 1] = acc11;
}

__global__ void gemm_M_kernel(const float* __restrict__ Km) {
    __shared__ float sA[32][33];
    __shared__ float sK[32][33];
    int tx = threadIdx.x, ty = threadIdx.y;
    int t = ty * 16 + tx;
    int b0 = blockIdx.y * 32, n0 = blockIdx.x * 32;
    float acc00 = 0.f, acc01 = 0.f, acc10 = 0.f, acc11 = 0.f;
    for (int kc = 0; kc < Ss; kc += 32) {
        #pragma unroll
        for (int l = t; l < 1024; l += 256) {
            int r = l >> 5, c = l & 31;
            sA[r][c] = g_A[(b0 + r) * Ss + kc + c];
            sK[r][c] = Km[(kc + r) * Nn + n0 + c];
        }
        __syncthreads();
        #pragma unroll
        for (int kk = 0; kk < 32; kk++) {
            float a0 = sA[2 * ty][kk],     a1 = sA[2 * ty + 1][kk];
            float b0v = sK[kk][2 * tx],    b1v = sK[kk][2 * tx + 1];
            acc00 = fmaf(a0, b0v, acc00);
            acc01 = fmaf(a0, b1v, acc01);
            acc10 = fmaf(a1, b0v, acc10);
            acc11 = fmaf(a1, b1v, acc11);
        }
        __syncthreads();
    }
    g_M[(b0 + 2 * ty)     * Nn + n0 + 2 * tx]     = acc00;
    g_M[(b0 + 2 * ty)     * Nn + n0 + 2 * tx + 1] = acc01;
    g_M[(b0 + 2 * ty + 1) * Nn + n0 + 2 * tx]     = acc10;
    g_M[(b0 + 2 * ty + 1) * Nn + n0 + 2 * tx + 1] = acc11;
}

// ---------------------------------------------------------------------------
__device__ __forceinline__ void cp_async16(uint32_t saddr, const void* gptr) {
    asm volatile("cp.async.cg.shared.global [%0], [%1], 16;\n"
                 :: "r"(saddr), "l"(gptr));
}
__device__ __forceinline__ uint32_t f2tf(float x) {
    uint32_t r;
    asm("cvt.rna.tf32.f32 %0, %1;" : "=r"(r) : "f"(x));
    return r;
}
__device__ __forceinline__ void tfsplit(float x, uint32_t& hi, uint32_t& lo) {
    hi = f2tf(x);
    lo = f2tf(x - __uint_as_float(hi));
}
__device__ __forceinline__ void mma_tf32(float* c, const uint32_t* a,
                                         uint32_t b0, uint32_t b1) {
    asm volatile(
        "mma.sync.aligned.m16n8k8.row.col.f32.tf32.tf32.f32 "
        "{%0,%1,%2,%3}, {%4,%5,%6,%7}, {%8,%9}, {%0,%1,%2,%3};"
        : "+f"(c[0]), "+f"(c[1]), "+f"(c[2]), "+f"(c[3])
        : "r"(a[0]), "r"(a[1]), "r"(a[2]), "r"(a[3]), "r"(b0), "r"(b1));
}

// ---------------------------------------------------------------------------
// A pre-split: g_M -> tf32 hi/lo in mma fragment order.
__global__ void afrag_kernel() {
    int wg = blockIdx.x * 8 + (threadIdx.x >> 5);   // kg*16 + mtile
    int l  = threadIdx.x & 31;
    int m0 = (wg & 15) * 16 + (l >> 2);
    int k0 = (wg >> 4) * 8 + (l & 3);
    float x0 = g_M[m0 * Nn + k0];
    float x1 = g_M[(m0 + 8) * Nn + k0];
    float x2 = g_M[m0 * Nn + k0 + 4];
    float x3 = g_M[(m0 + 8) * Nn + k0 + 4];
    uint4 h, lo;
    tfsplit(x0, h.x, lo.x); tfsplit(x1, h.y, lo.y);
    tfsplit(x2, h.z, lo.z); tfsplit(x3, h.w, lo.w);
    *(uint4*)(g_Ahi + (size_t)(wg * 32 + l) * 4) = h;
    *(uint4*)(g_Alo + (size_t)(wg * 32 + l) * 4) = lo;
}

// ---------------------------------------------------------------------------
// K1: 3-pass tf32 mma.sync, R11 structure, but MMAs issued PASS-MAJOR:
// all 8 independent hi*hi first, then hi*lo, then lo*hi -> same-acc reuse is
// 8 MMAs apart, covering tensor latency with per-warp ILP.
__global__ void __launch_bounds__(512, 1)
wpre_mma_kernel(const float* __restrict__ FV, float* __restrict__ Wout) {
    extern __shared__ float smem[];
    uint32_t* smu = (uint32_t*)smem;
    const int i  = blockIdx.z;
    const int mt = blockIdx.y;
    const int nt = blockIdx.x;
    const int b0 = mt * 128;
    const int d0 = nt * 128;
    const int tid = threadIdx.x;
    const int w = tid >> 5, l = tid & 31;
    const int mw = w & 3, nw = w >> 2;
    const int cks = w >> 2, cjp = (w & 3) * 2;
    const float* FVi = FV + (size_t)i * Nn * Dd;
    const uint32_t sbase = (uint32_t)__cvta_generic_to_shared(smem);

    #pragma unroll
    for (int k = 0; k < 2; k++) {
        int v = tid + 512 * k;
        int r = v >> 5, c4 = v & 31;
        cp_async16(sbase + (uint32_t)(r * STG_P + c4 * 4) * 4,
                   FVi + (size_t)r * Dd + d0 + c4 * 4);
    }
    asm volatile("cp.async.commit_group;\n");

    float acc[2][4][4];
    #pragma unroll
    for (int a = 0; a < 2; a++)
        #pragma unroll
        for (int b = 0; b < 4; b++)
            #pragma unroll
            for (int c = 0; c < 4; c++) acc[a][b][c] = 0.f;

    for (int c = 0; c < 8; c++) {
        if (c + 1 < 8) {
            const float* src = FVi + (size_t)(c + 1) * 32 * Dd + d0;
            uint32_t dst = sbase + (uint32_t)(((c + 1) & 1) * 32 * STG_P) * 4;
            #pragma unroll
            for (int k = 0; k < 2; k++) {
                int v = tid + 512 * k;
                int r = v >> 5, c4 = v & 31;
                cp_async16(dst + (uint32_t)(r * STG_P + c4 * 4) * 4,
                           src + (size_t)r * Dd + c4 * 4);
            }
            asm volatile("cp.async.commit_group;\n");
            asm volatile("cp.async.wait_group 1;\n");
        } else {
            asm volatile("cp.async.wait_group 0;\n");
        }
        __syncthreads();

        const float* stg = smem + OFF_STAGE + (c & 1) * 32 * STG_P;
        #pragma unroll
        for (int jj = 0; jj < 2; jj++) {
            int jp = cjp + jj;
            uint4 h, lo;
            #pragma unroll
            for (int sub = 0; sub < 4; sub++) {
                int j = jp * 2 + (sub >> 1);
                int r = sub & 1;
                int k = cks * 8 + r * 4 + (l & 3);
                int d = j * 8 + (l >> 2);
                float x = stg[k * STG_P + d];
                tfsplit(x, ((uint32_t*)&h)[sub], ((uint32_t*)&lo)[sub]);
            }
            int word = ((cks * 8 + jp) * 32 + l) * 4;
            *(uint4*)(smu + OFF_BFH + word) = h;
            *(uint4*)(smu + OFF_BFL + word) = lo;
        }
        __syncthreads();

        #pragma unroll
        for (int ks = 0; ks < 4; ks++) {
            const int kg = c * 4 + ks;
            uint4 ah[2], al[2];
            #pragma unroll
            for (int mi = 0; mi < 2; mi++) {
                int mtile = mt * 8 + mw * 2 + mi;
                size_t aw = (size_t)((kg * 16 + mtile) * 32 + l) * 4;
                ah[mi] = *(const uint4*)(g_Ahi + aw);
                al[mi] = *(const uint4*)(g_Alo + aw);
            }
            uint4 bh[2], bl[2];
            #pragma unroll
            for (int p = 0; p < 2; p++) {
                int word = ((ks * 8 + nw * 2 + p) * 32 + l) * 4;
                bh[p] = *(const uint4*)(smu + OFF_BFH + word);
                bl[p] = *(const uint4*)(smu + OFF_BFL + word);
            }
            // PASS-MAJOR issue: 8 independent MMAs per pass; same-acc reuse
            // spaced a full pass apart.
            #pragma unroll
            for (int pass = 0; pass < 3; pass++) {
                #pragma unroll
                for (int mi = 0; mi < 2; mi++) {
                    #pragma unroll
                    for (int j = 0; j < 4; j++) {
                        int p = j >> 1, hf = j & 1;
                        uint32_t b0v, b1v;
                        if (pass == 1) {        // ah x bl
                            b0v = hf ? bl[p].z : bl[p].x;
                            b1v = hf ? bl[p].w : bl[p].y;
                        } else {                // passes 0,2 use bh
                            b0v = hf ? bh[p].z : bh[p].x;
                            b1v = hf ? bh[p].w : bh[p].y;
                        }
                        const uint32_t* av = (pass == 2)
                            ? (const uint32_t*)&al[mi]
                            : (const uint32_t*)&ah[mi];
                        mma_tf32(acc[mi][j], av, b0v, b1v);
                    }
                }
            }
        }
        __syncthreads();
    }
    __syncthreads();

    // ---- epilogue: per-row tile stats + pre-softmax W store
    float* fm   = smem + OFF_RED;
    float* redm = fm + 128;
    float* reds = redm + 512;

    #pragma unroll
    for (int mi = 0; mi < 2; mi++) {
        #pragma unroll
        for (int h = 0; h < 2; h++) {
            float m = -3.4e38f;
            #pragma unroll
            for (int j = 0; j < 4; j++)
                m = fmaxf(m, fmaxf(acc[mi][j][2 * h], acc[mi][j][2 * h + 1]));
            m = fmaxf(m, __shfl_xor_sync(0xffffffffu, m, 1));
            m = fmaxf(m, __shfl_xor_sync(0xffffffffu, m, 2));
            if ((l & 3) == 0)
                redm[nw * 128 + mw * 32 + mi * 16 + (l >> 2) + 8 * h] = m;
        }
    }
    __syncthreads();
    if (tid < 128)
        fm[tid] = fmaxf(fmaxf(redm[tid], redm[128 + tid]),
                        fmaxf(redm[256 + tid], redm[384 + tid]));
    __syncthreads();
    #pragma unroll
    for (int mi = 0; mi < 2; mi++) {
        #pragma unroll
        for (int h = 0; h < 2; h++) {
            int row = mw * 32 + mi * 16 + (l >> 2) + 8 * h;
            float m = fm[row];
            float s = 0.f;
            #pragma unroll
            for (int j = 0; j < 4; j++)
                s += __expf(acc[mi][j][2 * h] - m) + __expf(acc[mi][j][2 * h + 1] - m);
            s += __shfl_xor_sync(0xffffffffu, s, 1);
            s += __shfl_xor_sync(0xffffffffu, s, 2);
            if ((l & 3) == 0) reds[nw * 128 + row] = s;
        }
    }
    __syncthreads();
    if (tid < 128) {
        int sidx = (((i * Bq) + b0 + tid) * 8 + nt) * 2;
        g_stats[sidx]     = fm[tid];
        g_stats[sidx + 1] = (reds[tid] + reds[128 + tid])
                          + (reds[256 + tid] + reds[384 + tid]);
    }
    #pragma unroll
    for (int mi = 0; mi < 2; mi++) {
        #pragma unroll
        for (int h = 0; h < 2; h++) {
            int row = mw * 32 + mi * 16 + (l >> 2) + 8 * h;
            float* wr = Wout + ((size_t)i * Bq + b0 + row) * Dd
                      + d0 + nw * 32 + 2 * (l & 3);
            #pragma unroll
            for (int j = 0; j < 4; j++)
                *(float2*)(wr + j * 8) =
                    make_float2(acc[mi][j][2 * h], acc[mi][j][2 * h + 1]);
        }
    }
}

// ---------------------------------------------------------------------------
// K2: float4 streaming, 4-way b-split for MLP, ldcs/stcs hints (R11-proven).
__global__ void __launch_bounds__(512, 2)
softmax_ctx_kernel(const float* __restrict__ FV,
                   float* __restrict__ W,
                   float* __restrict__ ctx) {
    __shared__ float  sm_m[256], sm_inv[256];
    __shared__ float4 cpart[4][128];
    const int i  = blockIdx.y;
    const int dh = blockIdx.x;
    const int t  = threadIdx.x;
    const int g  = t >> 7;          // b-group 0..3
    const int tl = t & 127;
    const int d  = dh * 512 + tl * 4;

    if (t < 256) {
        int b = t;
        const float* st = g_stats + (size_t)(i * Bq + b) * 16;
        float m = st[0];
        #pragma unroll
        for (int k = 1; k < 8; k++) m = fmaxf(m, st[2 * k]);
        float s = 0.f;
        #pragma unroll
        for (int k = 0; k < 8; k++) s += st[2 * k + 1] * __expf(st[2 * k] - m);
        sm_m[b]   = m;
        sm_inv[b] = 1.f / s;
    }
    __syncthreads();

    const float4* Wv  = (const float4*)(W  + (size_t)i * Bq * Dd + d);
    float4*       Wo  = (float4*)(W  + (size_t)i * Bq * Dd + d);
    const float4* FVv = (const float4*)(FV + (size_t)i * Nn * Dd + d);
    const int strd = Dd / 4;

    float4 acc = make_float4(0.f, 0.f, 0.f, 0.f);
    #pragma unroll 4
    for (int it = 0; it < 64; it++) {
        int b = g + it * 4;
        float4 x = __ldcs(Wv + (size_t)b * strd);
        float m = sm_m[b], inv = sm_inv[b];
        float4 wv;
        wv.x = __expf(x.x - m) * inv;
        wv.y = __expf(x.y - m) * inv;
        wv.z = __expf(x.z - m) * inv;
        wv.w = __expf(x.w - m) * inv;
        __stcs(Wo + (size_t)b * strd, wv);
        float4 f = __ldcs(FVv + (size_t)b * strd);
        acc.x = fmaf(wv.x, f.x, acc.x);
        acc.y = fmaf(wv.y, f.y, acc.y);
        acc.z = fmaf(wv.z, f.z, acc.z);
        acc.w = fmaf(wv.w, f.w, acc.w);
    }
    cpart[g][tl] = acc;
    __syncthreads();
    if (g == 0) {
        float4 a0 = cpart[0][tl], a1 = cpart[1][tl];
        float4 a2 = cpart[2][tl], a3 = cpart[3][tl];
        float4 r;
        r.x = (a0.x + a1.x) + (a2.x + a3.x);
        r.y = (a0.y + a1.y) + (a2.y + a3.y);
        r.z = (a0.z + a1.z) + (a2.z + a3.z);
        r.w = (a0.w + a1.w) + (a2.w + a3.w);
        *(float4*)(ctx + (size_t)i * Dd + d) = r;
    }
}

// ---------------------------------------------------------------------------
extern "C" void kernel_launch(void* const* d_in, const int* in_sizes, int n_in,
                              void* d_out, int out_size) {
    const float* FV    = (const float*)d_in[0];
    const float* state = (const float*)d_in[1];
    const float* Q     = (const float*)d_in[2];
    const float* Km    = (const float*)d_in[3];
    float* out = (float*)d_out;

    const long long wsz = (long long)Bq * Bq * Dd;
    float* ctxp;
    float* Wp;
    if ((long long)out_size == wsz) {
        Wp = out;
        cudaGetSymbolAddress((void**)&ctxp, g_ctx_scratch);
    } else {
        ctxp = out;
        Wp   = out + (size_t)Bq * Dd;
    }

    cudaFuncSetAttribute(wpre_mma_kernel,
                         cudaFuncAttributeMaxDynamicSharedMemorySize, SMEM_BYTES);

    gemm_A_kernel<<<dim3(Ss / 32, Bq / 32), dim3(16, 16)>>>(state, Q);
    gemm_M_kernel<<<dim3(Nn / 32, Bq / 32), dim3(16, 16)>>>(Km);
    afrag_kernel<<<64, 256>>>();
    wpre_mma_kernel<<<dim3(8, 2, 256), 512, SMEM_BYTES>>>(FV, Wp);
    softmax_ctx_kernel<<<dim3(2, 256), 512>>>(FV, Wp, ctxp);
}

// round 16
// speedup vs baseline: 1.3583x; 1.3379x over previous
#include <cuda_runtime.h>
#include <cuda_bf16.h>
#include <cstdint>

#define Bq 256
#define Nn 256
#define Dd 1024
#define Ss 1024

// K1 smem layout (floats)
#define STG_P 132
#define OFF_STAGE 0
#define STAGE_F (2 * 32 * STG_P)       // 8448
#define OFF_BFH STAGE_F                // B frags hi: 32 units * 32 * 2 = 2048
#define OFF_BFL (OFF_BFH + 2048)
#define OFF_RED (OFF_BFL + 2048)       // fm[128] + redm[512] + reds[512]
#define SMEM_F (OFF_RED + 1152)
#define SMEM_BYTES (SMEM_F * 4)        // 54784 B

// Scratch (device globals — no allocation APIs anywhere)
__device__ float    g_A[Bq * Ss];
__device__ float    g_M[Bq * Nn];
__device__ uint32_t g_Ahi[Bq * Nn];        // A frags bf16x2 hi: [kg16][mt16][l32][4]
__device__ uint32_t g_Alo[Bq * Nn];        // A frags bf16x2 lo
__device__ float    g_stats[Bq * Bq * 16]; // per (i,b,nt 0..7): m, s
__device__ float    g_ctx_scratch[Bq * Dd];

// ---------------------------------------------------------------------------
__global__ void gemm_A_kernel(const float* __restrict__ state,
                              const float* __restrict__ Q) {
    __shared__ float sS[32][33];
    __shared__ float sQ[32][33];
    int tx = threadIdx.x, ty = threadIdx.y;
    int t = ty * 16 + tx;
    int b0 = blockIdx.y * 32, s0 = blockIdx.x * 32;
    float acc00 = 0.f, acc01 = 0.f, acc10 = 0.f, acc11 = 0.f;
    for (int k0 = 0; k0 < Ss; k0 += 32) {
        #pragma unroll
        for (int l = t; l < 1024; l += 256) {
            int r = l >> 5, c = l & 31;
            sS[r][c] = state[(b0 + r) * Ss + k0 + c];
            sQ[r][c] = Q[(s0 + r) * Ss + k0 + c];
        }
        __syncthreads();
        #pragma unroll
        for (int kk = 0; kk < 32; kk++) {
            float a0 = sS[2 * ty][kk],     a1 = sS[2 * ty + 1][kk];
            float q0 = sQ[2 * tx][kk],     q1 = sQ[2 * tx + 1][kk];
            acc00 = fmaf(a0, q0, acc00);
            acc01 = fmaf(a0, q1, acc01);
            acc10 = fmaf(a1, q0, acc10);
            acc11 = fmaf(a1, q1, acc11);
        }
        __syncthreads();
    }
    g_A[(b0 + 2 * ty)     * Ss + s0 + 2 * tx]     = acc00;
    g_A[(b0 + 2 * ty)     * Ss + s0 + 2 * tx + 1] = acc01;
    g_A[(b0 + 2 * ty + 1) * Ss + s0 + 2 * tx]     = acc10;
    g_A[(b0 + 2 * ty + 1) * Ss + s0 + 2 * tx + 1] = acc11;
}

__global__ void gemm_M_kernel(const float* __restrict__ Km) {
    __shared__ float sA[32][33];
    __shared__ float sK[32][33];
    int tx = threadIdx.x, ty = threadIdx.y;
    int t = ty * 16 + tx;
    int b0 = blockIdx.y * 32, n0 = blockIdx.x * 32;
    float acc00 = 0.f, acc01 = 0.f, acc10 = 0.f, acc11 = 0.f;
    for (int kc = 0; kc < Ss; kc += 32) {
        #pragma unroll
        for (int l = t; l < 1024; l += 256) {
            int r = l >> 5, c = l & 31;
            sA[r][c] = g_A[(b0 + r) * Ss + kc + c];
            sK[r][c] = Km[(kc + r) * Nn + n0 + c];
        }
        __syncthreads();
        #pragma unroll
        for (int kk = 0; kk < 32; kk++) {
            float a0 = sA[2 * ty][kk],     a1 = sA[2 * ty + 1][kk];
            float b0v = sK[kk][2 * tx],    b1v = sK[kk][2 * tx + 1];
            acc00 = fmaf(a0, b0v, acc00);
            acc01 = fmaf(a0, b1v, acc01);
            acc10 = fmaf(a1, b0v, acc10);
            acc11 = fmaf(a1, b1v, acc11);
        }
        __syncthreads();
    }
    g_M[(b0 + 2 * ty)     * Nn + n0 + 2 * tx]     = acc00;
    g_M[(b0 + 2 * ty)     * Nn + n0 + 2 * tx + 1] = acc01;
    g_M[(b0 + 2 * ty + 1) * Nn + n0 + 2 * tx]     = acc10;
    g_M[(b0 + 2 * ty + 1) * Nn + n0 + 2 * tx + 1] = acc11;
}

// ---------------------------------------------------------------------------
__device__ __forceinline__ void cp_async16(uint32_t saddr, const void* gptr) {
    asm volatile("cp.async.cg.shared.global [%0], [%1], 16;\n"
                 :: "r"(saddr), "l"(gptr));
}
// split (x0,x1) into packed bf16x2 hi and lo (lo = residual after hi)
__device__ __forceinline__ void bfsplit2(float x0, float x1,
                                         uint32_t& hi, uint32_t& lo) {
    uint32_t h;
    asm("cvt.rn.bf16x2.f32 %0, %1, %2;" : "=r"(h) : "f"(x1), "f"(x0));
    float h0 = __uint_as_float(h << 16);
    float h1 = __uint_as_float(h & 0xFFFF0000u);
    float r0 = x0 - h0, r1 = x1 - h1;
    asm("cvt.rn.bf16x2.f32 %0, %1, %2;" : "=r"(lo) : "f"(r1), "f"(r0));
    hi = h;
}
__device__ __forceinline__ void mma_bf16(float* c, const uint32_t* a,
                                         uint32_t b0, uint32_t b1) {
    asm volatile(
        "mma.sync.aligned.m16n8k16.row.col.f32.bf16.bf16.f32 "
        "{%0,%1,%2,%3}, {%4,%5,%6,%7}, {%8,%9}, {%0,%1,%2,%3};"
        : "+f"(c[0]), "+f"(c[1]), "+f"(c[2]), "+f"(c[3])
        : "r"(a[0]), "r"(a[1]), "r"(a[2]), "r"(a[3]), "r"(b0), "r"(b1));
}

// ---------------------------------------------------------------------------
// A pre-split: g_M -> bf16x2 hi/lo fragments [kg16][mtile16][lane32][4].
// m16n8k16 A layout: a0=(m, k0..k0+1), a1=(m+8, ..), a2=(m, k0+8..9), a3=(m+8,..)
__global__ void afrag_kernel() {
    int wg = blockIdx.x * 8 + (threadIdx.x >> 5);   // kg*16 + mtile, 256 total
    int l  = threadIdx.x & 31;
    int mtile = wg & 15, kg = wg >> 4;
    int m0 = mtile * 16 + (l >> 2);
    int k0 = kg * 16 + (l & 3) * 2;
    uint4 h, lo;
    bfsplit2(g_M[m0 * Nn + k0],           g_M[m0 * Nn + k0 + 1],       h.x, lo.x);
    bfsplit2(g_M[(m0 + 8) * Nn + k0],     g_M[(m0 + 8) * Nn + k0 + 1], h.y, lo.y);
    bfsplit2(g_M[m0 * Nn + k0 + 8],       g_M[m0 * Nn + k0 + 9],       h.z, lo.z);
    bfsplit2(g_M[(m0 + 8) * Nn + k0 + 8], g_M[(m0 + 8) * Nn + k0 + 9], h.w, lo.w);
    *(uint4*)(g_Ahi + (size_t)(wg * 32 + l) * 4) = h;
    *(uint4*)(g_Alo + (size_t)(wg * 32 + l) * 4) = lo;
}

// ---------------------------------------------------------------------------
// K1: 3-pass bf16 mma.sync (m16n8k16). CTA=(nt,mt,i): C[128 m][128 d],
// k=256 in 8 chunks of 32. 16 warps as 4m x 4n, warp tile 32x32.
// 48 MMAs/warp/chunk (was 96 with tf32 k8).
__global__ void __launch_bounds__(512, 1)
wpre_mma_kernel(const float* __restrict__ FV, float* __restrict__ Wout) {
    extern __shared__ float smem[];
    uint32_t* smu = (uint32_t*)smem;
    const int i  = blockIdx.z;
    const int mt = blockIdx.y;
    const int nt = blockIdx.x;
    const int b0 = mt * 128;
    const int d0 = nt * 128;
    const int tid = threadIdx.x;
    const int w = tid >> 5, l = tid & 31;
    const int mw = w & 3, nw = w >> 2;
    const float* FVi = FV + (size_t)i * Nn * Dd;
    const uint32_t sbase = (uint32_t)__cvta_generic_to_shared(smem);

    #pragma unroll
    for (int k = 0; k < 2; k++) {
        int v = tid + 512 * k;
        int r = v >> 5, c4 = v & 31;
        cp_async16(sbase + (uint32_t)(r * STG_P + c4 * 4) * 4,
                   FVi + (size_t)r * Dd + d0 + c4 * 4);
    }
    asm volatile("cp.async.commit_group;\n");

    float acc[2][4][4];
    #pragma unroll
    for (int a = 0; a < 2; a++)
        #pragma unroll
        for (int b = 0; b < 4; b++)
            #pragma unroll
            for (int c = 0; c < 4; c++) acc[a][b][c] = 0.f;

    for (int c = 0; c < 8; c++) {
        if (c + 1 < 8) {
            const float* src = FVi + (size_t)(c + 1) * 32 * Dd + d0;
            uint32_t dst = sbase + (uint32_t)(((c + 1) & 1) * 32 * STG_P) * 4;
            #pragma unroll
            for (int k = 0; k < 2; k++) {
                int v = tid + 512 * k;
                int r = v >> 5, c4 = v & 31;
                cp_async16(dst + (uint32_t)(r * STG_P + c4 * 4) * 4,
                           src + (size_t)r * Dd + c4 * 4);
            }
            asm volatile("cp.async.commit_group;\n");
            asm volatile("cp.async.wait_group 1;\n");
        } else {
            asm volatile("cp.async.wait_group 0;\n");
        }
        __syncthreads();

        // convert B chunk: 32 units (kg2 x jt16); warp w does units 2w, 2w+1.
        // B frag (m16n8k16): b0=(k=(l&3)*2+{0,1}, n=l>>2), b1=(k+8, n).
        const float* stg = smem + OFF_STAGE + (c & 1) * 32 * STG_P;
        #pragma unroll
        for (int uu = 0; uu < 2; uu++) {
            int u = w * 2 + uu;
            int kg = u >> 4, jt = u & 15;
            int k0 = kg * 16 + (l & 3) * 2;
            int d  = jt * 8 + (l >> 2);
            uint32_t b0h, b0l, b1h, b1l;
            bfsplit2(stg[k0 * STG_P + d],       stg[(k0 + 1) * STG_P + d], b0h, b0l);
            bfsplit2(stg[(k0 + 8) * STG_P + d], stg[(k0 + 9) * STG_P + d], b1h, b1l);
            int word = ((kg * 16 + jt) * 32 + l) * 2;
            *(uint2*)(smu + OFF_BFH + word) = make_uint2(b0h, b1h);
            *(uint2*)(smu + OFF_BFL + word) = make_uint2(b0l, b1l);
        }
        __syncthreads();

        #pragma unroll
        for (int kg = 0; kg < 2; kg++) {
            const int kgG = c * 2 + kg;
            uint4 ah[2], al[2];
            #pragma unroll
            for (int mi = 0; mi < 2; mi++) {
                int mtile = mt * 8 + mw * 2 + mi;
                size_t aw = (size_t)((kgG * 16 + mtile) * 32 + l) * 4;
                ah[mi] = *(const uint4*)(g_Ahi + aw);
                al[mi] = *(const uint4*)(g_Alo + aw);
            }
            uint2 bh[4], bl[4];
            #pragma unroll
            for (int j = 0; j < 4; j++) {
                int word = ((kg * 16 + nw * 4 + j) * 32 + l) * 2;
                bh[j] = *(const uint2*)(smu + OFF_BFH + word);
                bl[j] = *(const uint2*)(smu + OFF_BFL + word);
            }
            #pragma unroll
            for (int mi = 0; mi < 2; mi++) {
                #pragma unroll
                for (int j = 0; j < 4; j++) {
                    mma_bf16(acc[mi][j], (const uint32_t*)&ah[mi], bh[j].x, bh[j].y);
                    mma_bf16(acc[mi][j], (const uint32_t*)&ah[mi], bl[j].x, bl[j].y);
                    mma_bf16(acc[mi][j], (const uint32_t*)&al[mi], bh[j].x, bh[j].y);
                }
            }
        }
        __syncthreads();
    }
    __syncthreads();

    // ---- epilogue: per-row tile stats + pre-softmax W store (unchanged)
    float* fm   = smem + OFF_RED;
    float* redm = fm + 128;
    float* reds = redm + 512;

    #pragma unroll
    for (int mi = 0; mi < 2; mi++) {
        #pragma unroll
        for (int h = 0; h < 2; h++) {
            float m = -3.4e38f;
            #pragma unroll
            for (int j = 0; j < 4; j++)
                m = fmaxf(m, fmaxf(acc[mi][j][2 * h], acc[mi][j][2 * h + 1]));
            m = fmaxf(m, __shfl_xor_sync(0xffffffffu, m, 1));
            m = fmaxf(m, __shfl_xor_sync(0xffffffffu, m, 2));
            if ((l & 3) == 0)
                redm[nw * 128 + mw * 32 + mi * 16 + (l >> 2) + 8 * h] = m;
        }
    }
    __syncthreads();
    if (tid < 128)
        fm[tid] = fmaxf(fmaxf(redm[tid], redm[128 + tid]),
                        fmaxf(redm[256 + tid], redm[384 + tid]));
    __syncthreads();
    #pragma unroll
    for (int mi = 0; mi < 2; mi++) {
        #pragma unroll
        for (int h = 0; h < 2; h++) {
            int row = mw * 32 + mi * 16 + (l >> 2) + 8 * h;
            float m = fm[row];
            float s = 0.f;
            #pragma unroll
            for (int j = 0; j < 4; j++)
                s += __expf(acc[mi][j][2 * h] - m) + __expf(acc[mi][j][2 * h + 1] - m);
            s += __shfl_xor_sync(0xffffffffu, s, 1);
            s += __shfl_xor_sync(0xffffffffu, s, 2);
            if ((l & 3) == 0) reds[nw * 128 + row] = s;
        }
    }
    __syncthreads();
    if (tid < 128) {
        int sidx = (((i * Bq) + b0 + tid) * 8 + nt) * 2;
        g_stats[sidx]     = fm[tid];
        g_stats[sidx + 1] = (reds[tid] + reds[128 + tid])
                          + (reds[256 + tid] + reds[384 + tid]);
    }
    #pragma unroll
    for (int mi = 0; mi < 2; mi++) {
        #pragma unroll
        for (int h = 0; h < 2; h++) {
            int row = mw * 32 + mi * 16 + (l >> 2) + 8 * h;
            float* wr = Wout + ((size_t)i * Bq + b0 + row) * Dd
                      + d0 + nw * 32 + 2 * (l & 3);
            #pragma unroll
            for (int j = 0; j < 4; j++)
                *(float2*)(wr + j * 8) =
                    make_float2(acc[mi][j][2 * h], acc[mi][j][2 * h + 1]);
        }
    }
}

// ---------------------------------------------------------------------------
// K2: float4 streaming, 4-way b-split for MLP, ldcs/stcs hints (R11-proven).
__global__ void __launch_bounds__(512, 2)
softmax_ctx_kernel(const float* __restrict__ FV,
                   float* __restrict__ W,
                   float* __restrict__ ctx) {
    __shared__ float  sm_m[256], sm_inv[256];
    __shared__ float4 cpart[4][128];
    const int i  = blockIdx.y;
    const int dh = blockIdx.x;
    const int t  = threadIdx.x;
    const int g  = t >> 7;          // b-group 0..3
    const int tl = t & 127;
    const int d  = dh * 512 + tl * 4;

    if (t < 256) {
        int b = t;
        const float* st = g_stats + (size_t)(i * Bq + b) * 16;
        float m = st[0];
        #pragma unroll
        for (int k = 1; k < 8; k++) m = fmaxf(m, st[2 * k]);
        float s = 0.f;
        #pragma unroll
        for (int k = 0; k < 8; k++) s += st[2 * k + 1] * __expf(st[2 * k] - m);
        sm_m[b]   = m;
        sm_inv[b] = 1.f / s;
    }
    __syncthreads();

    const float4* Wv  = (const float4*)(W  + (size_t)i * Bq * Dd + d);
    float4*       Wo  = (float4*)(W  + (size_t)i * Bq * Dd + d);
    const float4* FVv = (const float4*)(FV + (size_t)i * Nn * Dd + d);
    const int strd = Dd / 4;

    float4 acc = make_float4(0.f, 0.f, 0.f, 0.f);
    #pragma unroll 4
    for (int it = 0; it < 64; it++) {
        int b = g + it * 4;
        float4 x = __ldcs(Wv + (size_t)b * strd);
        float m = sm_m[b], inv = sm_inv[b];
        float4 wv;
        wv.x = __expf(x.x - m) * inv;
        wv.y = __expf(x.y - m) * inv;
        wv.z = __expf(x.z - m) * inv;
        wv.w = __expf(x.w - m) * inv;
        __stcs(Wo + (size_t)b * strd, wv);
        float4 f = __ldcs(FVv + (size_t)b * strd);
        acc.x = fmaf(wv.x, f.x, acc.x);
        acc.y = fmaf(wv.y, f.y, acc.y);
        acc.z = fmaf(wv.z, f.z, acc.z);
        acc.w = fmaf(wv.w, f.w, acc.w);
    }
    cpart[g][tl] = acc;
    __syncthreads();
    if (g == 0) {
        float4 a0 = cpart[0][tl], a1 = cpart[1][tl];
        float4 a2 = cpart[2][tl], a3 = cpart[3][tl];
        float4 r;
        r.x = (a0.x + a1.x) + (a2.x + a3.x);
        r.y = (a0.y + a1.y) + (a2.y + a3.y);
        r.z = (a0.z + a1.z) + (a2.z + a3.z);
        r.w = (a0.w + a1.w) + (a2.w + a3.w);
        *(float4*)(ctx + (size_t)i * Dd + d) = r;
    }
}

// ---------------------------------------------------------------------------
extern "C" void kernel_launch(void* const* d_in, const int* in_sizes, int n_in,
                              void* d_out, int out_size) {
    const float* FV    = (const float*)d_in[0];
    const float* state = (const float*)d_in[1];
    const float* Q     = (const float*)d_in[2];
    const float* Km    = (const float*)d_in[3];
    float* out = (float*)d_out;

    const long long wsz = (long long)Bq * Bq * Dd;
    float* ctxp;
    float* Wp;
    if ((long long)out_size == wsz) {
        Wp = out;
        cudaGetSymbolAddress((void**)&ctxp, g_ctx_scratch);
    } else {
        ctxp = out;
        Wp   = out + (size_t)Bq * Dd;
    }

    cudaFuncSetAttribute(wpre_mma_kernel,
                         cudaFuncAttributeMaxDynamicSharedMemorySize, SMEM_BYTES);

    gemm_A_kernel<<<dim3(Ss / 32, Bq / 32), dim3(16, 16)>>>(state, Q);
    gemm_M_kernel<<<dim3(Nn / 32, Bq / 32), dim3(16, 16)>>>(Km);
    afrag_kernel<<<32, 256>>>();
    wpre_mma_kernel<<<dim3(8, 2, 256), 512, SMEM_BYTES>>>(FV, Wp);
    softmax_ctx_kernel<<<dim3(2, 256), 512>>>(FV, Wp, ctxp);
}